// round 4
// baseline (speedup 1.0000x reference)
#include <cuda_runtime.h>
#include <cuda_bf16.h>

#define LGT    16
#define NROWS  4096
#define DCOLS  16000          // CLASSNUM * LGT
#define CHUNKS 2              // chunks per row
#define NBLK   (NROWS * CHUNKS)           // 8192 CTAs
#define VEC_PER_CHUNK (DCOLS / 4 / CHUNKS) // 2000 float4

__device__ float        g_acc = 0.0f;
__device__ unsigned int g_cnt = 0u;

__global__ __launch_bounds__(256, 8)
void rvsml_loss_kernel(const float* __restrict__ inputs,
                       const float* __restrict__ labels,
                       float* __restrict__ out) {
    const int bid   = blockIdx.x;
    const int row   = bid >> 1;       // CHUNKS == 2
    const int half  = bid & 1;
    const int tid   = threadIdx.x;

    // ---- Stream this chunk of the row, sum of squares ----
    const float4* chunkp = reinterpret_cast<const float4*>(inputs + (size_t)row * DCOLS)
                         + half * VEC_PER_CHUNK;
    float acc = 0.0f;
    #pragma unroll 4
    for (int i = tid; i < VEC_PER_CHUNK; i += 256) {
        float4 v = chunkp[i];
        acc = fmaf(v.x, v.x, acc);
        acc = fmaf(v.y, v.y, acc);
        acc = fmaf(v.z, v.z, acc);
        acc = fmaf(v.w, v.w, acc);
    }

    // ---- Block reduce acc -> chunk sum of squares ----
    __shared__ float warp_sums[8];
    #pragma unroll
    for (int off = 16; off > 0; off >>= 1)
        acc += __shfl_xor_sync(0xFFFFFFFFu, acc, off);
    if ((tid & 31) == 0) warp_sums[tid >> 5] = acc;
    __syncthreads();

    // ---- Warp 0: weights, (chunk-0 only) gather term, global accumulate ----
    if (tid < 32) {
        float v = (tid < 8) ? warp_sums[tid] : 0.0f;
        #pragma unroll
        for (int off = 4; off > 0; off >>= 1)
            v += __shfl_xor_sync(0xFFFFFFFFu, v, off);
        const float sq_chunk = __shfl_sync(0xFFFFFFFFu, v, 0);

        // labels row: lanes 0..15 = weights, lane 16 = class id
        float lv = 0.0f;
        if (tid <= LGT) lv = __ldg(labels + row * (LGT + 1) + tid);
        const int   c = (int)__shfl_sync(0xFFFFFFFFu, lv, LGT);
        const float w = (tid < LGT) ? lv : 0.0f;

        // extra = w_j * (1 - 2*g_j), only counted once per row (chunk 0)
        float extra = 0.0f;
        if (half == 0 && tid < LGT) {
            const float g = __ldg(inputs + (size_t)row * DCOLS + c * LGT + tid);
            extra = w * (1.0f - 2.0f * g);
        }

        // reduce (W = sum of w lanes) and (extra) together
        float w_red = w, e_red = extra;
        #pragma unroll
        for (int off = 16; off > 0; off >>= 1) {
            w_red += __shfl_xor_sync(0xFFFFFFFFu, w_red, off);
            e_red += __shfl_xor_sync(0xFFFFFFFFu, e_red, off);
        }

        if (tid == 0) {
            const float contrib = w_red * sq_chunk + e_red;
            atomicAdd(&g_acc, contrib);
            __threadfence();
            const unsigned ticket = atomicAdd(&g_cnt, 1u);
            if (ticket == NBLK - 1) {
                // All contributions are visible (each CTA fenced before its
                // counter increment). Read + reset for the next graph replay.
                const float total = atomicExch(&g_acc, 0.0f);
                out[0] = total * (1.0f / (float)NROWS);
                g_cnt = 0u;
                __threadfence();
            }
        }
    }
}

extern "C" void kernel_launch(void* const* d_in, const int* in_sizes, int n_in,
                              void* d_out, int out_size) {
    const float* inputs = (const float*)d_in[0];
    const float* labels = (const float*)d_in[1];
    float* out = (float*)d_out;

    rvsml_loss_kernel<<<NBLK, 256>>>(inputs, labels, out);
}

// round 5
// speedup vs baseline: 1.0430x; 1.0430x over previous
#include <cuda_runtime.h>
#include <cuda_bf16.h>

#define LGT   16
#define NROWS 4096
#define DCOLS 16000   // CLASSNUM * LGT

__device__ float        g_acc = 0.0f;
__device__ unsigned int g_cnt = 0u;

__global__ __launch_bounds__(256)
void rvsml_loss_kernel(const float* __restrict__ inputs,
                       const float* __restrict__ labels,
                       float* __restrict__ out) {
    const int row = blockIdx.x;
    const int tid = threadIdx.x;

    // Occupancy limiter: 44KB smem/CTA -> 4 CTAs/SM (228KB budget).
    // Reduces cross-CTA L1tex-queue contention (B300 spread model) and
    // makes 4096 CTAs / (148*4) = 6.9 waves (1% tail waste vs 13.5% at occ 8).
    __shared__ float warp_sums[8];
    __shared__ float sq_sh;
    __shared__ char  occ_pad[44 * 1024];
    if (tid == 1024) sq_sh = (float)occ_pad[0];  // never true; keeps pad live

    // ---- Stream the row, accumulate sum of squares ----
    const float4* rowp = reinterpret_cast<const float4*>(inputs + (size_t)row * DCOLS);
    const int nvec = DCOLS / 4;  // 4000

    float acc = 0.0f;
    #pragma unroll 4
    for (int i = tid; i < nvec; i += 256) {
        float4 v = rowp[i];
        acc = fmaf(v.x, v.x, acc);
        acc = fmaf(v.y, v.y, acc);
        acc = fmaf(v.z, v.z, acc);
        acc = fmaf(v.w, v.w, acc);
    }

    // ---- Block reduce acc -> sq ----
    #pragma unroll
    for (int off = 16; off > 0; off >>= 1)
        acc += __shfl_xor_sync(0xFFFFFFFFu, acc, off);
    if ((tid & 31) == 0) warp_sums[tid >> 5] = acc;
    __syncthreads();

    if (tid < 32) {
        float v = (tid < 8) ? warp_sums[tid] : 0.0f;
        #pragma unroll
        for (int off = 4; off > 0; off >>= 1)
            v += __shfl_xor_sync(0xFFFFFFFFu, v, off);
        if (tid == 0) sq_sh = v;
    }
    __syncthreads();

    // ---- Gather + weighted contribution (warp 0; row is L2-resident) ----
    if (tid < 32) {
        const float sq = sq_sh;
        const float* lab = labels + row * (LGT + 1);
        float contrib = 0.0f;
        if (tid < LGT) {
            const int c = (int)lab[LGT];
            const float w = lab[tid];
            const float g = inputs[(size_t)row * DCOLS + c * LGT + tid];
            contrib = w * (sq + 1.0f - 2.0f * g);
        }
        #pragma unroll
        for (int off = 16; off > 0; off >>= 1)
            contrib += __shfl_xor_sync(0xFFFFFFFFu, contrib, off);

        if (tid == 0) {
            atomicAdd(&g_acc, contrib);
            __threadfence();
            const unsigned ticket = atomicAdd(&g_cnt, 1u);
            if (ticket == NROWS - 1) {
                // All contributions visible (each CTA fenced before its
                // counter increment). Read + reset for the next graph replay.
                const float total = atomicExch(&g_acc, 0.0f);
                out[0] = total * (1.0f / (float)NROWS);
                g_cnt = 0u;
                __threadfence();
            }
        }
    }
}

extern "C" void kernel_launch(void* const* d_in, const int* in_sizes, int n_in,
                              void* d_out, int out_size) {
    const float* inputs = (const float*)d_in[0];
    const float* labels = (const float*)d_in[1];
    float* out = (float*)d_out;

    rvsml_loss_kernel<<<NROWS, 256>>>(inputs, labels, out);
}